// round 1
// baseline (speedup 1.0000x reference)
#include <cuda_runtime.h>

// WOS (weighted order statistic) 3x3 filter.
// Per (pixel, channel): mx[54] = [patch(27), -patch(27)] + mask[c][:],
// sort descending (carrying weight[c][:]), cumsum weights>ZERO_TOL in sorted
// order, pick last sorted value with accw <= bias[c] (or first nz if none).
//
// Exactness: the cumulative sum is performed in the reference's sorted order,
// so the accw <= bias tests match the JAX reference bit-for-bit (ties in mx
// are measure-zero for random inputs).

#define NCH 16
#define DD 54
#define HH 64
#define WW 64
#define PIX_PER_BLK 8
#define NTHREADS (NCH * PIX_PER_BLK)   // 128
#define TILE_COLS (PIX_PER_BLK + 2)    // 10
#define TILE_ELEMS (3 * 3 * TILE_COLS) // 90
#define ZTOL 1e-6f

__global__ __launch_bounds__(NTHREADS)
void wos_kernel(const float* __restrict__ x,
                const float* __restrict__ mask,
                const float* __restrict__ weight,
                const float* __restrict__ bias,
                float* __restrict__ out)
{
    __shared__ float tile_s[TILE_ELEMS];
    __shared__ float msk_s[NCH * DD];
    __shared__ float w_s[NCH * DD];
    __shared__ float bias_s[NCH];

    const int tid = threadIdx.x;
    const int c  = tid & (NCH - 1);   // channel (lane%16)
    const int ty = tid >> 4;          // pixel within block (0..7)

    const int pix0 = blockIdx.x * PIX_PER_BLK;
    const int b    = pix0 >> 12;          // / 4096
    const int rem  = pix0 & 4095;
    const int h    = rem >> 6;
    const int w0   = rem & 63;            // multiple of 8, no row crossing

    // ---- cooperative staging ----
    #pragma unroll
    for (int idx = tid; idx < NCH * DD; idx += NTHREADS) {
        msk_s[idx] = mask[idx];
        w_s[idx]   = weight[idx];
    }
    if (tid < NCH) bias_s[tid] = bias[tid];
    for (int idx = tid; idx < TILE_ELEMS; idx += NTHREADS) {
        int cc  = idx / (3 * TILE_COLS);
        int r   = (idx / TILE_COLS) % 3;
        int col = idx % TILE_COLS;
        int gh = h + r - 1;
        int gw = w0 + col - 1;
        float v = 0.0f;
        if (gh >= 0 && gh < HH && gw >= 0 && gw < WW)
            v = x[((b * 3 + cc) * HH + gh) * WW + gw];
        tile_s[idx] = v;
    }
    __syncthreads();

    // ---- build mx / w in registers ----
    float val[DD];
    float wv[DD];
    const float* mrow = &msk_s[c * DD];
    const float* wrow = &w_s[c * DD];

    #pragma unroll
    for (int cc = 0; cc < 3; cc++) {
        #pragma unroll
        for (int i = 0; i < 3; i++) {
            #pragma unroll
            for (int j = 0; j < 3; j++) {
                const int d0 = cc * 9 + i * 3 + j;
                float v = tile_s[(cc * 3 + i) * TILE_COLS + ty + j];
                val[d0]      = v + mrow[d0];
                val[27 + d0] = mrow[27 + d0] - v;
                wv[d0]       = wrow[d0];
                wv[27 + d0]  = wrow[27 + d0];
            }
        }
    }

    // ---- Batcher odd-even merge sort, descending, n=54 (in registers) ----
    // Valid restriction of the 64-wire network: virtual -inf padding at
    // indices >= 54 never moves under max-at-low-index compare-exchange.
    #pragma unroll
    for (int p = 1; p < DD; p <<= 1) {
        #pragma unroll
        for (int k = p; k >= 1; k >>= 1) {
            #pragma unroll
            for (int j = k % p; j + k < DD; j += 2 * k) {
                #pragma unroll
                for (int i = 0; i < k; i++) {
                    const int a  = i + j;
                    const int bb = i + j + k;
                    if (bb < DD && (a / (2 * p)) == (bb / (2 * p))) {
                        float va = val[a], vb = val[bb];
                        bool sw = vb > va;
                        val[a]  = fmaxf(va, vb);
                        val[bb] = fminf(va, vb);
                        float wa = wv[a], wb = wv[bb];
                        wv[a]  = sw ? wb : wa;
                        wv[bb] = sw ? wa : wb;
                    }
                }
            }
        }
    }

    // ---- cumsum in sorted order + selection (bitwise matches reference) ----
    const float bs = bias_s[c];
    float acc = 0.0f;
    int   licnt = 0;
    float ans = 0.0f;
    float first_nz = 0.0f;
    bool  seen = false;

    #pragma unroll
    for (int k2 = 0; k2 < DD; k2++) {
        float wk = wv[k2];
        if (wk > ZTOL) {
            acc += wk;
            if (!seen) { first_nz = val[k2]; seen = true; }
            if (acc <= bs) { ans = val[k2]; licnt++; }
        }
    }
    float y = (licnt > 0) ? ans : first_nz;

    // reference does a raw .view(B, NC, H, W) of an (N, NC) buffer:
    // out_flat = b*65536 + (h*64+w)*16 + c   -> channel fastest, coalesced.
    const int l = h * WW + (w0 + ty);
    out[b * (NCH * HH * WW) + l * NCH + c] = y;
}

extern "C" void kernel_launch(void* const* d_in, const int* in_sizes, int n_in,
                              void* d_out, int out_size)
{
    const float* x      = (const float*)d_in[0];
    const float* mask   = (const float*)d_in[1];
    const float* weight = (const float*)d_in[2];
    const float* bias   = (const float*)d_in[3];
    float* out = (float*)d_out;

    // B derived from input size: x is (B, 3, 64, 64)
    const int B = in_sizes[0] / (3 * HH * WW);
    const int npix = B * HH * WW;
    dim3 grid(npix / PIX_PER_BLK);
    wos_kernel<<<grid, NTHREADS>>>(x, mask, weight, bias, out);
}